// round 6
// baseline (speedup 1.0000x reference)
#include <cuda_runtime.h>
#include <math.h>

#define Lr 1024
#define Br 32
#define Dr 256
#define LAMf 0.2f
#define NR (Lr*Br)

// Scratch (device globals). BATCH-MAJOR row index r = b*Lr + i.
__device__ float g_K[NR*5];      // K[i, j=i+d-2], d=0..4
__device__ float g_S[NR];        // row sums of K
__device__ float g_E[NR];        // per-row cost numerator: sum_d K*(1-cos)

// ---------------------------------------------------------------- fused: zero-fill P (+cost slots) + band compute
__global__ void kfused(const float* __restrict__ m1, const float* __restrict__ m2,
                       const int* __restrict__ lengths, float4* __restrict__ out) {
    int bid = blockIdx.x;
    int tid = threadIdx.x;
    int rem = bid % 3;
    if (rem != 2) {
        int zid = (bid / 3) * 2 + rem;                 // [0, 8192)
        out[(size_t)zid * 256 + tid] = make_float4(0.f, 0.f, 0.f, 0.f);
        if (bid == 0 && tid < Br)                      // zero the 32 cost slots
            ((float*)out)[(size_t)Br * Lr * Lr + tid] = 0.0f;
        return;
    }
    int w = (bid / 3) * 8 + (tid >> 5);                // input row (i,b), w in [0, NR)
    int lane = tid & 31;
    int b = w & 31;
    int i = w >> 5;
    int rr = b * Lr + i;                               // batch-major scratch index
    int l = __ldg(lengths + b);
    if (i >= l) {
        if (lane == 0) {
            g_S[rr] = 1.0f; g_E[rr] = 0.0f;
            #pragma unroll
            for (int d = 0; d < 5; d++) g_K[rr*5+d] = 0.0f;
        }
        return;
    }
    const float4* xp = (const float4*)(m1 + (size_t)w * Dr);
    float4 xa = xp[lane], xb = xp[lane + 32];
    float xx = xa.x*xa.x + xa.y*xa.y + xa.z*xa.z + xa.w*xa.w
             + xb.x*xb.x + xb.y*xb.y + xb.z*xb.z + xb.w*xb.w;
    #pragma unroll
    for (int o = 16; o; o >>= 1) xx += __shfl_xor_sync(0xffffffffu, xx, o);
    float nx = fmaxf(sqrtf(xx), 1e-5f);

    float S = 0.0f, E = 0.0f;
    float Ks[5];
    #pragma unroll
    for (int d = 0; d < 5; d++) {
        int j = i + d - 2;
        float Kv = 0.0f;
        if (j >= 0 && j < l) {
            const float4* yp = (const float4*)(m2 + ((size_t)(j*Br + b)) * Dr);
            float4 ya = yp[lane], yb = yp[lane + 32];
            float dot = xa.x*ya.x + xa.y*ya.y + xa.z*ya.z + xa.w*ya.w
                      + xb.x*yb.x + xb.y*yb.y + xb.z*yb.z + xb.w*yb.w;
            float yy  = ya.x*ya.x + ya.y*ya.y + ya.z*ya.z + ya.w*ya.w
                      + yb.x*yb.x + yb.y*yb.y + yb.z*yb.z + yb.w*yb.w;
            #pragma unroll
            for (int o = 16; o; o >>= 1) {
                dot += __shfl_xor_sync(0xffffffffu, dot, o);
                yy  += __shfl_xor_sync(0xffffffffu, yy,  o);
            }
            float ny = fmaxf(sqrtf(yy), 1e-5f);
            float Mv = 1.0f - dot / (nx * ny);
            Kv = expf(-LAMf * Mv);
            E += Kv * Mv;
        }
        Ks[d] = Kv; S += Kv;
    }
    if (lane == 0) {
        g_S[rr] = S; g_E[rr] = E;
        #pragma unroll
        for (int d = 0; d < 5; d++) g_K[rr*5+d] = Ks[d];
    }
}

// ---------------------------------------------------------------- tiled t + cost + band scatter
// grid = Br*8 blocks of 160 threads; block = (batch b, tile of 128 rows).
#define TPB 160
#define TILE 128
__global__ void ktc(const int* __restrict__ lengths, float* __restrict__ out) {
    __shared__ float sh_K[136*5];
    __shared__ float sh_invS[136];
    __shared__ float sh_t[132];
    __shared__ float sh_c[TILE];
    int bid = blockIdx.x;
    int tid = threadIdx.x;
    int b = bid >> 3;
    int j0 = (bid & 7) * TILE;
    int h0 = j0 - 4;                 // K/S halo start (136 rows)
    int base = b * Lr;
    int l = __ldg(lengths + b);

    // stage K halo (680 floats) + invS halo (136)
    for (int idx = tid; idx < 136*5; idx += TPB) {
        int i = h0 + idx / 5;
        if (i >= 0 && i < Lr) sh_K[idx] = g_K[(size_t)(base + i) * 5 + idx % 5];
    }
    for (int idx = tid; idx < 136; idx += TPB) {
        int i = h0 + idx;
        sh_invS[idx] = (i >= 0 && i < Lr) ? (1.0f / g_S[base + i]) : 1.0f;
    }
    __syncthreads();

    // t for rows [j0-2, j0+130)
    if (tid < 132) {
        int jt = j0 - 2 + tid;
        float t = 1.0f;
        if (jt >= 0 && jt < l) {
            t = 0.0f;
            #pragma unroll
            for (int dd = 0; dd < 5; dd++) {
                int i = jt + dd - 2;
                if (i >= 0 && i < l) {
                    int s = tid + dd;                  // i - h0
                    t += sh_K[s*5 + (4 - dd)] * sh_invS[s];
                }
            }
        }
        sh_t[tid] = t;
    }
    __syncthreads();

    // own rows: scatter band + cost term
    float term = 0.0f;
    if (tid < TILE) {
        int j = j0 + tid;
        if (j < l) {
            int s = tid + 4;                           // j - h0  (FIX: was tid+6)
            float invS = sh_invS[s];
            float t    = sh_t[tid + 2];
            float rt   = 1.0f / t;
            float inv  = invS * rt;
            term = g_E[base + j] * invS * rt / (float)l;
            float* Po = out + (size_t)b * Lr * Lr + (size_t)j * Lr;
            #pragma unroll
            for (int d = 0; d < 5; d++) {
                int jj = j + d - 2;
                if (jj >= 0 && jj < l)
                    Po[jj] = sh_K[s*5 + d] * sh_t[tid + d] * inv;
            }
        }
        sh_c[tid] = term;
    }
    __syncthreads();
    #pragma unroll
    for (int s = TILE/2; s; s >>= 1) {
        if (tid < s) sh_c[tid] += sh_c[tid + s];
        __syncthreads();
    }
    if (tid == 0) atomicAdd(out + (size_t)Br * Lr * Lr + b, sh_c[0]);
}

extern "C" void kernel_launch(void* const* d_in, const int* in_sizes, int n_in,
                              void* d_out, int out_size) {
    const float* m1      = (const float*)d_in[0];
    const float* m2      = (const float*)d_in[1];
    const int*   lengths = (const int*)d_in[2];
    float* out = (float*)d_out;

    kfused<<<12288, 256>>>(m1, m2, lengths, (float4*)out);  // zero P + cost slots + band math
    ktc<<<Br*8, TPB>>>(lengths, out);                       // tiled t + cost + band scatter
}